// round 3
// baseline (speedup 1.0000x reference)
#include <cuda_runtime.h>

#define IN_CH   256
#define OUT_CH  256
#define NTASKS  64
#define WSIZE   (OUT_CH * IN_CH)
#define FULL_EMBED (WSIZE + OUT_CH)
#define BMAX    4096
#define MT      32                       // rows per tile
#define NCOLS   64                       // output cols per CTA
#define XST     34                       // Xsm row stride (conflict-free, 8B-aligned)
#define MAXTILES 192                     // sum ceil(n_i/32) <= (4096 + 64*31)/32 = 190

#define WSM_F   (IN_CH * NCOLS)          // 16384 floats = 64KB
#define XSM_F   (IN_CH * XST)            // 8704 floats  = 34KB
#define SMEM_B  ((WSM_F + XSM_F) * 4)    // ~100KB -> 2 CTAs/SM

// ---- global scratch (static __device__, allocation-free) ----
__device__ int g_list[BMAX];             // sample indices grouped by task
__device__ int g_tile_task[MAXTILES];
__device__ int g_tile_start[MAXTILES];
__device__ int g_tile_len[MAXTILES];
__device__ int g_ntiles;

// ================= Kernel A: build compact lists + tile work-list ==========
__global__ void build_lists(const int* __restrict__ ids, int B) {
    __shared__ int cnt[NTASKS], cur[NTASKS];
    __shared__ int s_tt[MAXTILES], s_ts[MAXTILES], s_tl[MAXTILES];
    __shared__ int s_nt;
    int tid = threadIdx.x;
    if (tid < NTASKS) cnt[tid] = 0;
    __syncthreads();

    for (int i = tid; i < B; i += blockDim.x)
        atomicAdd(&cnt[ids[i]], 1);
    __syncthreads();

    if (tid == 0) {
        int acc = 0, nt = 0;
        for (int t = 0; t < NTASKS; t++) {
            cur[t] = acc;
            int n = cnt[t];
            for (int m0 = 0; m0 < n; m0 += MT) {
                s_tt[nt] = t;
                s_ts[nt] = acc + m0;
                s_tl[nt] = (n - m0 < MT) ? (n - m0) : MT;
                nt++;
            }
            acc += n;
        }
        s_nt = nt;
    }
    __syncthreads();

    for (int i = tid; i < B; i += blockDim.x) {
        int t = ids[i];
        int pos = atomicAdd(&cur[t], 1);
        g_list[pos] = i;
    }
    int nt = s_nt;
    for (int i = tid; i < MAXTILES; i += blockDim.x) {
        if (i < nt) {
            g_tile_task[i]  = s_tt[i];
            g_tile_start[i] = s_ts[i];
            g_tile_len[i]   = s_tl[i];
        }
    }
    if (tid == 0) g_ntiles = nt;
}

// ================= f32x2 helpers ===========================================
__device__ __forceinline__ unsigned long long fma2(unsigned long long a,
                                                   unsigned long long b,
                                                   unsigned long long c) {
    unsigned long long d;
    asm("fma.rn.f32x2 %0, %1, %2, %3;" : "=l"(d) : "l"(a), "l"(b), "l"(c));
    return d;
}
__device__ __forceinline__ unsigned long long pack2(float x) {
    unsigned long long d;
    asm("mov.b64 %0, {%1, %1};" : "=l"(d) : "f"(x));
    return d;
}
__device__ __forceinline__ float2 unpack2(unsigned long long v) {
    float2 r;
    asm("mov.b64 {%0, %1}, %2;" : "=f"(r.x), "=f"(r.y) : "l"(v));
    return r;
}

// ================= Kernel B: one (tile, col-chunk) per CTA =================
__global__ __launch_bounds__(256, 2)
void affine_tile_kernel(const float* __restrict__ inputs,
                        const float* __restrict__ te,
                        float* __restrict__ out) {
    extern __shared__ float smem[];
    float* Wsm = smem;                 // [k][c]  (256 x 64)
    float* Xsm = smem + WSM_F;         // [k][r]  (256 x XST)

    const int ty = blockIdx.y;
    if (ty >= g_ntiles) return;
    const int task    = g_tile_task[ty];
    const int start   = g_tile_start[ty];
    const int len     = g_tile_len[ty];
    const int colBase = blockIdx.x * NCOLS;
    const int tid     = threadIdx.x;

    const float* emb = te + (size_t)task * FULL_EMBED;

    // ---- W stage: 64 cols x 256 k, transposed to [k][c] ----
    {
        int c  = tid & (NCOLS - 1);
        int ks = (tid >> 6) * 64;
        const float4* wg = (const float4*)(emb + (size_t)(colBase + c) * IN_CH + ks);
        #pragma unroll
        for (int kv = 0; kv < 16; kv++) {
            float4 v = wg[kv];
            int k = ks + kv * 4;
            Wsm[(k + 0) * NCOLS + c] = v.x;
            Wsm[(k + 1) * NCOLS + c] = v.y;
            Wsm[(k + 2) * NCOLS + c] = v.z;
            Wsm[(k + 3) * NCOLS + c] = v.w;
        }
    }
    // ---- X stage: up to 32 rows, transposed to [k][r] ----
    {
        int r  = tid & 31;
        int ks = (tid >> 5) * 32;
        if (r < len) {
            int gi = g_list[start + r];
            const float4* xg = (const float4*)(inputs + (size_t)gi * IN_CH + ks);
            #pragma unroll
            for (int kv = 0; kv < 8; kv++) {
                float4 v = xg[kv];
                int k = ks + kv * 4;
                Xsm[(k + 0) * XST + r] = v.x;
                Xsm[(k + 1) * XST + r] = v.y;
                Xsm[(k + 2) * XST + r] = v.z;
                Xsm[(k + 3) * XST + r] = v.w;
            }
        } else {
            #pragma unroll
            for (int kv = 0; kv < 8; kv++) {
                int k = ks + kv * 4;
                Xsm[(k + 0) * XST + r] = 0.0f;
                Xsm[(k + 1) * XST + r] = 0.0f;
                Xsm[(k + 2) * XST + r] = 0.0f;
                Xsm[(k + 3) * XST + r] = 0.0f;
            }
        }
    }
    __syncthreads();

    // ---- thread tile: 2 rows x 4 cols ----
    const int g  = tid & 15;
    const int r0 = (tid >> 4) * 2;
    const int c0 = g * 4;

    unsigned long long a00 = 0, a01 = 0, a10 = 0, a11 = 0;
    const float* xp = Xsm + r0;
    const float* wp = Wsm + c0;
    #pragma unroll 8
    for (int k = 0; k < IN_CH; k++) {
        float2 xv = *(const float2*)xp;
        ulonglong2 w = *(const ulonglong2*)wp;
        unsigned long long x0 = pack2(xv.x);
        unsigned long long x1 = pack2(xv.y);
        a00 = fma2(w.x, x0, a00);
        a01 = fma2(w.y, x0, a01);
        a10 = fma2(w.x, x1, a10);
        a11 = fma2(w.y, x1, a11);
        xp += XST;
        wp += NCOLS;
    }

    const float b0 = emb[WSIZE + colBase + c0 + 0];
    const float b1 = emb[WSIZE + colBase + c0 + 1];
    const float b2 = emb[WSIZE + colBase + c0 + 2];
    const float b3 = emb[WSIZE + colBase + c0 + 3];

    if (r0 < len) {
        float* orow = out + (size_t)g_list[start + r0] * OUT_CH + colBase + c0;
        float2 v = unpack2(a00); v.x += b0; v.y += b1; *(float2*)orow       = v;
        v        = unpack2(a01); v.x += b2; v.y += b3; *(float2*)(orow + 2) = v;
    }
    if (r0 + 1 < len) {
        float* orow = out + (size_t)g_list[start + r0 + 1] * OUT_CH + colBase + c0;
        float2 v = unpack2(a10); v.x += b0; v.y += b1; *(float2*)orow       = v;
        v        = unpack2(a11); v.x += b2; v.y += b3; *(float2*)(orow + 2) = v;
    }
}

// ================= launch ==================================================
extern "C" void kernel_launch(void* const* d_in, const int* in_sizes, int n_in,
                              void* d_out, int out_size) {
    const float* inputs   = (const float*)d_in[0];
    const int*   task_ids = (const int*)d_in[1];   // JAX x64 disabled -> int32
    const float* te       = (const float*)d_in[2];
    float*       out      = (float*)d_out;
    int B = in_sizes[1];

    build_lists<<<1, 1024>>>(task_ids, B);

    cudaFuncSetAttribute(affine_tile_kernel,
                         cudaFuncAttributeMaxDynamicSharedMemorySize, SMEM_B);
    dim3 grid(OUT_CH / NCOLS, MAXTILES, 1);   // (4, 192)
    affine_tile_kernel<<<grid, 256, SMEM_B>>>(inputs, te, out);
}

// round 4
// speedup vs baseline: 1.4992x; 1.4992x over previous
#include <cuda_runtime.h>

#define IN_CH   256
#define OUT_CH  256
#define NTASKS  64
#define WSIZE   (OUT_CH * IN_CH)
#define FULL_EMBED (WSIZE + OUT_CH)
#define BMAX    4096
#define MT      32                        // rows per X tile
#define NCOLS   64                        // output cols per CTA
#define THREADS 64
#define XSTRIDE 260                       // floats per X row (16B aligned, 2-way max)

#define WSM_F   (IN_CH * NCOLS)           // 16384 floats = 64KB, layout [k][c]
#define XSM_F   (MT * XSTRIDE)            // 8320 floats ~ 33.3KB, layout [r][k]
#define SMEM_B  ((WSM_F + XSM_F) * 4)     // ~97.3KB -> 2 CTAs/SM

// ---- global scratch ----
__device__ int g_list[BMAX];              // sample idx grouped by task
__device__ int g_off[NTASKS];
__device__ int g_cnt[NTASKS];

// ================= prep: group samples by task =============================
__global__ void build_lists(const int* __restrict__ ids, int B) {
    __shared__ int cnt[NTASKS], cur[NTASKS];
    int tid = threadIdx.x;
    if (tid < NTASKS) cnt[tid] = 0;
    __syncthreads();
    for (int i = tid; i < B; i += blockDim.x) atomicAdd(&cnt[ids[i]], 1);
    __syncthreads();
    if (tid == 0) {
        int acc = 0;
        for (int t = 0; t < NTASKS; t++) {
            cur[t] = acc; g_off[t] = acc; g_cnt[t] = cnt[t]; acc += cnt[t];
        }
    }
    __syncthreads();
    for (int i = tid; i < B; i += blockDim.x) {
        int t = ids[i];
        g_list[atomicAdd(&cur[t], 1)] = i;
    }
}

// ================= f32x2 helpers ===========================================
__device__ __forceinline__ unsigned long long fma2(unsigned long long a,
                                                   unsigned long long b,
                                                   unsigned long long c) {
    unsigned long long d;
    asm("fma.rn.f32x2 %0, %1, %2, %3;" : "=l"(d) : "l"(a), "l"(b), "l"(c));
    return d;
}
__device__ __forceinline__ unsigned long long pack2(float x) {
    unsigned long long d;
    asm("mov.b64 %0, {%1, %1};" : "=l"(d) : "f"(x));
    return d;
}
__device__ __forceinline__ float2 unpack2(unsigned long long v) {
    float2 r;
    asm("mov.b64 {%0, %1}, %2;" : "=f"(r.x), "=f"(r.y) : "l"(v));
    return r;
}

// ================= main: CTA = (task, 64-col chunk) ========================
__global__ __launch_bounds__(THREADS, 2)
void affine_kernel(const float* __restrict__ inputs,
                   const float* __restrict__ te,
                   float* __restrict__ out) {
    extern __shared__ float smem[];
    float* Wsm = smem;                 // [k][c] : Wsm[k*64 + c] = W[colBase+c][k]
    float* Xsm = smem + WSM_F;         // [r][k] : Xsm[r*XSTRIDE + k]

    const int task    = blockIdx.y;
    const int colBase = blockIdx.x * NCOLS;
    const int tid     = threadIdx.x;
    const int lane    = tid & 31;
    const int warp    = tid >> 5;

    const int n     = g_cnt[task];
    if (n == 0) return;
    const int start = g_off[task];

    const float* emb = te + (size_t)task * FULL_EMBED;

    // ---- stage W transposed: thread = one column, conflict-free STS ----
    {
        const int c = tid;             // 0..63
        const float4* wg = (const float4*)(emb + (size_t)(colBase + c) * IN_CH);
        #pragma unroll
        for (int kv = 0; kv < 64; kv++) {
            float4 v = wg[kv];
            int k = kv * 4;
            Wsm[(k + 0) * NCOLS + c] = v.x;
            Wsm[(k + 1) * NCOLS + c] = v.y;
            Wsm[(k + 2) * NCOLS + c] = v.z;
            Wsm[(k + 3) * NCOLS + c] = v.w;
        }
    }

    // ---- thread tile mapping: 4 rows x 8 cols ----
    const int g  = tid & 7;            // col group
    const int rg = tid >> 3;           // row group 0..7
    const int r0 = rg * 4;
    const int cA = g * 4;
    const int cB = 32 + g * 4;

    float biasA[4], biasB[4];
    #pragma unroll
    for (int j = 0; j < 4; j++) {
        biasA[j] = emb[WSIZE + colBase + cA + j];
        biasB[j] = emb[WSIZE + colBase + cB + j];
    }

    // ---- loop over 32-row tiles of this task ----
    for (int m0 = 0; m0 < n; m0 += MT) {
        __syncthreads();   // Xsm reusable (also covers W stage on first iter)

        // stage X: warp-per-row halves, coalesced LDG + linear STS
        {
            // each warp handles 16 rows; per row: 32 lanes x 8 floats = 2 float4
            for (int rr = 0; rr < 16; rr++) {
                int r = warp * 16 + rr;
                int row = m0 + r;
                float* xrow = Xsm + r * XSTRIDE;
                if (row < n) {
                    const float4* xg = (const float4*)(inputs + (size_t)g_list[start + row] * IN_CH);
                    float4 v0 = xg[lane];
                    float4 v1 = xg[lane + 32];
                    ((float4*)xrow)[lane]      = v0;
                    ((float4*)xrow)[lane + 32] = v1;
                } else {
                    ((float4*)xrow)[lane]      = make_float4(0.f, 0.f, 0.f, 0.f);
                    ((float4*)xrow)[lane + 32] = make_float4(0.f, 0.f, 0.f, 0.f);
                }
            }
        }
        __syncthreads();

        unsigned long long acc[4][4];   // [row][colpair]: 2 pairs A, 2 pairs B
        #pragma unroll
        for (int i = 0; i < 4; i++)
            #pragma unroll
            for (int j = 0; j < 4; j++) acc[i][j] = 0ULL;

        const float* xbase = Xsm + r0 * XSTRIDE;
        const float* wbase = Wsm + cA;

        #pragma unroll 2
        for (int k = 0; k < IN_CH; k += 4) {
            // 4 rows x 4 k-values
            float4 xv0 = *(const float4*)(xbase + 0 * XSTRIDE + k);
            float4 xv1 = *(const float4*)(xbase + 1 * XSTRIDE + k);
            float4 xv2 = *(const float4*)(xbase + 2 * XSTRIDE + k);
            float4 xv3 = *(const float4*)(xbase + 3 * XSTRIDE + k);
            #pragma unroll
            for (int kk = 0; kk < 4; kk++) {
                const float* wp = wbase + (k + kk) * NCOLS;
                ulonglong2 wA = *(const ulonglong2*)wp;
                ulonglong2 wB = *(const ulonglong2*)(wp + 32);
                float x0 = (kk == 0) ? xv0.x : (kk == 1) ? xv0.y : (kk == 2) ? xv0.z : xv0.w;
                float x1 = (kk == 0) ? xv1.x : (kk == 1) ? xv1.y : (kk == 2) ? xv1.z : xv1.w;
                float x2 = (kk == 0) ? xv2.x : (kk == 1) ? xv2.y : (kk == 2) ? xv2.z : xv2.w;
                float x3 = (kk == 0) ? xv3.x : (kk == 1) ? xv3.y : (kk == 2) ? xv3.z : xv3.w;
                unsigned long long p0 = pack2(x0), p1 = pack2(x1);
                unsigned long long p2 = pack2(x2), p3 = pack2(x3);
                acc[0][0] = fma2(wA.x, p0, acc[0][0]);
                acc[0][1] = fma2(wA.y, p0, acc[0][1]);
                acc[0][2] = fma2(wB.x, p0, acc[0][2]);
                acc[0][3] = fma2(wB.y, p0, acc[0][3]);
                acc[1][0] = fma2(wA.x, p1, acc[1][0]);
                acc[1][1] = fma2(wA.y, p1, acc[1][1]);
                acc[1][2] = fma2(wB.x, p1, acc[1][2]);
                acc[1][3] = fma2(wB.y, p1, acc[1][3]);
                acc[2][0] = fma2(wA.x, p2, acc[2][0]);
                acc[2][1] = fma2(wA.y, p2, acc[2][1]);
                acc[2][2] = fma2(wB.x, p2, acc[2][2]);
                acc[2][3] = fma2(wB.y, p2, acc[2][3]);
                acc[3][0] = fma2(wA.x, p3, acc[3][0]);
                acc[3][1] = fma2(wA.y, p3, acc[3][1]);
                acc[3][2] = fma2(wB.x, p3, acc[3][2]);
                acc[3][3] = fma2(wB.y, p3, acc[3][3]);
            }
        }

        // ---- epilogue: 4 rows x 8 cols, two STG.128 per row ----
        #pragma unroll
        for (int j = 0; j < 4; j++) {
            int row = m0 + r0 + j;
            if (row < n) {
                float* orow = out + (size_t)g_list[start + row] * OUT_CH + colBase;
                float2 vA0 = unpack2(acc[j][0]);
                float2 vA1 = unpack2(acc[j][1]);
                float2 vB0 = unpack2(acc[j][2]);
                float2 vB1 = unpack2(acc[j][3]);
                float4 oA = make_float4(vA0.x + biasA[0], vA0.y + biasA[1],
                                        vA1.x + biasA[2], vA1.y + biasA[3]);
                float4 oB = make_float4(vB0.x + biasB[0], vB0.y + biasB[1],
                                        vB1.x + biasB[2], vB1.y + biasB[3]);
                *(float4*)(orow + cA) = oA;
                *(float4*)(orow + cB) = oB;
            }
        }
    }
}

// ================= launch ==================================================
extern "C" void kernel_launch(void* const* d_in, const int* in_sizes, int n_in,
                              void* d_out, int out_size) {
    const float* inputs   = (const float*)d_in[0];
    const int*   task_ids = (const int*)d_in[1];   // JAX x64 disabled -> int32
    const float* te       = (const float*)d_in[2];
    float*       out      = (float*)d_out;
    int B = in_sizes[1];

    build_lists<<<1, 1024>>>(task_ids, B);

    cudaFuncSetAttribute(affine_kernel,
                         cudaFuncAttributeMaxDynamicSharedMemorySize, SMEM_B);
    dim3 grid(OUT_CH / NCOLS, NTASKS, 1);   // (4, 64) = 256 CTAs, 2/SM
    affine_kernel<<<grid, THREADS, SMEM_B>>>(inputs, te, out);
}